// round 12
// baseline (speedup 1.0000x reference)
#include <cuda_runtime.h>

#define NPTS 32768

// ---------------------------------------------------------------------------
// Scratch: per-net optical depth tau[g][n]  (nets 7,8 are dead -> never written
// or read, but keep full 76 stride for simple indexing).
// ---------------------------------------------------------------------------
__device__ float g_tau[76 * NPTS];

// Active nets (h2o nets 7 and 8 are never referenced by H2O_IDX -> dead code).
__constant__ int c_net_id[74] = {
    0, 1, 2, 3, 4, 5, 6,
    9, 10, 11, 12, 13, 14, 15, 16, 17, 18, 19, 20, 21, 22, 23, 24, 25, 26, 27, 28,
    29, 30, 31, 32, 33, 34, 35, 36, 37, 38, 39, 40, 41,
    42, 43, 44, 45, 46, 47, 48, 49, 50,
    51, 52, 53,
    54, 55, 56, 57, 58, 59, 60, 61, 62,
    63, 64, 65, 66, 67, 68, 69, 70, 71, 72, 73, 74, 75
};

// Per-channel contributing nets (gather form of the reference scatter-adds),
// in the same accumulation order as the reference: h2o, o3, co2, n2o, ch4, u.
__constant__ int c_ch_cnt[29] = {
    6, 6, 6, 2, 2, 2, 2, 2, 2, 2, 2, 2, 2, 2, 2, 2, 2,
    3, 3, 3, 3, 3, 3, 1, 1, 2, 2, 3, 3
};
__constant__ int c_ch_nets[29][6] = {
    {0, 29, 42, 51, 54, 63}, {1, 30, 43, 52, 55, 64}, {2, 31, 44, 53, 56, 65},
    {3, 57, 0, 0, 0, 0},  {4, 58, 0, 0, 0, 0},  {5, 45, 0, 0, 0, 0},
    {6, 46, 0, 0, 0, 0},  {3, 59, 0, 0, 0, 0},  {4, 60, 0, 0, 0, 0},
    {9, 47, 0, 0, 0, 0},  {10, 48, 0, 0, 0, 0}, {11, 61, 0, 0, 0, 0},
    {12, 62, 0, 0, 0, 0}, {13, 49, 0, 0, 0, 0}, {14, 50, 0, 0, 0, 0},
    {15, 66, 0, 0, 0, 0}, {16, 67, 0, 0, 0, 0},
    {17, 32, 68, 0, 0, 0}, {18, 33, 69, 0, 0, 0}, {19, 34, 70, 0, 0, 0},
    {20, 35, 71, 0, 0, 0}, {21, 36, 72, 0, 0, 0}, {22, 37, 73, 0, 0, 0},
    {23, 0, 0, 0, 0, 0},  {24, 0, 0, 0, 0, 0},
    {25, 38, 0, 0, 0, 0}, {26, 39, 0, 0, 0, 0},
    {27, 40, 74, 0, 0, 0}, {28, 41, 75, 0, 0, 0}
};

// ---------------------------------------------------------------------------
// Packed fp32x2 helpers (Blackwell f32x2 path: 2 IEEE fp32 FMAs per issue).
// ---------------------------------------------------------------------------
__device__ __forceinline__ unsigned long long pack2(float lo, float hi) {
    unsigned long long r;
    asm("mov.b64 %0, {%1, %2};" : "=l"(r) : "f"(lo), "f"(hi));
    return r;
}
__device__ __forceinline__ void fma2(unsigned long long& d,
                                     unsigned long long a,
                                     unsigned long long b) {
    asm("fma.rn.f32x2 %0, %1, %2, %0;" : "+l"(d) : "l"(a), "l"(b));
}
__device__ __forceinline__ float2 unpack2(unsigned long long v) {
    float2 f;
    asm("mov.b64 {%0, %1}, %2;" : "=f"(f.x), "=f"(f.y) : "l"(v));
    return f;
}

// ---------------------------------------------------------------------------
// Pass 1: per-(net, point) fused MLP -> tau[g][n]
//   block = 128 threads, 1 point/thread; grid = (NPTS/128, 74)
//   W2[g] (64x64 fp32, 16 KB) staged in SMEM; 32 packed k-accumulators in regs;
//   h1[j] recomputed on the fly from broadcast SMEM (saves 64 regs).
// ---------------------------------------------------------------------------
__global__ __launch_bounds__(128, 3)
void mlp_tau_kernel(const float* __restrict__ t_p,
                    const float* __restrict__ comp,
                    const float* __restrict__ W1,
                    const float* __restrict__ b1,
                    const float* __restrict__ W2,
                    const float* __restrict__ b2,
                    const float* __restrict__ Wout,
                    const float* __restrict__ bout)
{
    __shared__ __align__(16) float sW2[64 * 64];
    __shared__ float sW1[128];
    __shared__ float sb1[64];
    __shared__ float sb2[64];
    __shared__ float swout[64];

    const int tid = threadIdx.x;
    const int g = c_net_id[blockIdx.y];

    // Stage weights for this net.
    {
        const float4* src = reinterpret_cast<const float4*>(W2 + g * 4096);
        float4* dst = reinterpret_cast<float4*>(sW2);
        #pragma unroll
        for (int i = 0; i < 8; i++) dst[tid + 128 * i] = src[tid + 128 * i];
        sW1[tid] = W1[g * 128 + tid];
        if (tid < 64) {
            sb1[tid]   = b1[g * 64 + tid];
            sb2[tid]   = b2[g * 64 + tid];
            swout[tid] = Wout[g * 64 + tid];
        }
    }
    __syncthreads();

    const int n = blockIdx.x * 128 + tid;
    const float2 t = reinterpret_cast<const float2*>(t_p)[n];

    // 32 packed accumulators over output-neuron pairs (k, k+1), init with b2.
    unsigned long long acc[32];
    #pragma unroll
    for (int kk = 0; kk < 32; kk++)
        acc[kk] = pack2(sb2[2 * kk], sb2[2 * kk + 1]);

    const ulonglong2* __restrict__ w2v = reinterpret_cast<const ulonglong2*>(sW2);

    // Main loop: for each hidden unit j, recompute h1[j], then rank-1 update
    // of all 64 layer-2 accumulators (32 packed FMA2 via broadcast LDS.128).
    #pragma unroll 4
    for (int j = 0; j < 64; j++) {
        float h = fmaf(t.x, sW1[j], fmaf(t.y, sW1[64 + j], sb1[j]));
        h = fmaxf(h, 0.0f);
        const unsigned long long hj = pack2(h, h);
        const ulonglong2* r = w2v + j * 16;
        #pragma unroll
        for (int q = 0; q < 16; q++) {
            ulonglong2 w = r[q];
            fma2(acc[2 * q],     hj, w.x);
            fma2(acc[2 * q + 1], hj, w.y);
        }
    }

    // Layer 3: ke = relu( sum_k relu(acc_k) * Wout_k + bout ), 4 partial chains.
    float ke0 = 0.f, ke1 = 0.f, ke2 = 0.f, ke3 = 0.f;
    #pragma unroll
    for (int kk = 0; kk < 32; kk++) {
        float2 a = unpack2(acc[kk]);
        a.x = fmaxf(a.x, 0.0f);
        a.y = fmaxf(a.y, 0.0f);
        if (kk & 1) {
            ke2 = fmaf(a.x, swout[2 * kk], ke2);
            ke3 = fmaf(a.y, swout[2 * kk + 1], ke3);
        } else {
            ke0 = fmaf(a.x, swout[2 * kk], ke0);
            ke1 = fmaf(a.y, swout[2 * kk + 1], ke1);
        }
    }
    const float ke = fmaxf((ke0 + ke2) + (ke1 + ke3) + bout[g], 0.0f);

    // COMP_IDX(g): repeat(arange(6), [29,13,9,3,9,13])
    const int cg = (g < 29) ? 0 : (g < 42) ? 1 : (g < 51) ? 2
                 : (g < 54) ? 3 : (g < 63) ? 4 : 5;

    g_tau[g * NPTS + n] = ke * comp[cg * NPTS + n];
}

// ---------------------------------------------------------------------------
// Pass 2: gather per-channel net contributions + the two broadcast products.
// Output layout: [tau_gases(29,N) | tau_lw(29,N) | tau_iw(29,N)]  fp32.
// ---------------------------------------------------------------------------
__global__ void combine_kernel(const float* __restrict__ comp,
                               const float* __restrict__ ke_lw,
                               const float* __restrict__ ke_iw,
                               float* __restrict__ out)
{
    const int c = blockIdx.y;
    const int n = blockIdx.x * blockDim.x + threadIdx.x;

    const int cnt = c_ch_cnt[c];
    float s = 0.0f;
    #pragma unroll
    for (int i = 0; i < 6; i++)
        if (i < cnt) s += g_tau[c_ch_nets[c][i] * NPTS + n];

    out[c * NPTS + n] = s;
    out[29 * NPTS + c * NPTS + n] = ke_lw[c] * comp[6 * NPTS + n];
    out[58 * NPTS + c * NPTS + n] = ke_iw[c] * comp[7 * NPTS + n];
}

// ---------------------------------------------------------------------------
// Launch contract
// ---------------------------------------------------------------------------
extern "C" void kernel_launch(void* const* d_in, const int* in_sizes, int n_in,
                              void* d_out, int out_size)
{
    const float* t_p   = (const float*)d_in[0];
    const float* comp  = (const float*)d_in[1];
    const float* W1    = (const float*)d_in[2];
    const float* b1    = (const float*)d_in[3];
    const float* W2    = (const float*)d_in[4];
    const float* b2    = (const float*)d_in[5];
    const float* Wout  = (const float*)d_in[6];
    const float* bout  = (const float*)d_in[7];
    const float* ke_lw = (const float*)d_in[8];
    const float* ke_iw = (const float*)d_in[9];
    float* out = (float*)d_out;

    dim3 grid1(NPTS / 128, 74);
    mlp_tau_kernel<<<grid1, 128>>>(t_p, comp, W1, b1, W2, b2, Wout, bout);

    dim3 grid2(NPTS / 256, 29);
    combine_kernel<<<grid2, 256>>>(comp, ke_lw, ke_iw, out);
}

// round 15
// speedup vs baseline: 3.2978x; 3.2978x over previous
#include <cuda_runtime.h>
#include <cuda_fp16.h>
#include <cstdint>

#define NPTS 32768
#define TILES_PER_CTA 16
#define CHUNKS 16          // CHUNKS * TILES_PER_CTA * 128 == NPTS

// ---------------------------------------------------------------------------
// Scratch: per-net optical depth tau[g][n]
// ---------------------------------------------------------------------------
__device__ float g_tau[76 * NPTS];

// Active nets (h2o nets 7,8 are dead: never referenced by H2O_IDX).
__constant__ int c_net_id[74] = {
    0, 1, 2, 3, 4, 5, 6,
    9, 10, 11, 12, 13, 14, 15, 16, 17, 18, 19, 20, 21, 22, 23, 24, 25, 26, 27, 28,
    29, 30, 31, 32, 33, 34, 35, 36, 37, 38, 39, 40, 41,
    42, 43, 44, 45, 46, 47, 48, 49, 50,
    51, 52, 53,
    54, 55, 56, 57, 58, 59, 60, 61, 62,
    63, 64, 65, 66, 67, 68, 69, 70, 71, 72, 73, 74, 75
};

// Per-channel contributing nets (gather form of the reference scatter-adds).
__constant__ int c_ch_cnt[29] = {
    6, 6, 6, 2, 2, 2, 2, 2, 2, 2, 2, 2, 2, 2, 2, 2, 2,
    3, 3, 3, 3, 3, 3, 1, 1, 2, 2, 3, 3
};
__constant__ int c_ch_nets[29][6] = {
    {0, 29, 42, 51, 54, 63}, {1, 30, 43, 52, 55, 64}, {2, 31, 44, 53, 56, 65},
    {3, 57, 0, 0, 0, 0},  {4, 58, 0, 0, 0, 0},  {5, 45, 0, 0, 0, 0},
    {6, 46, 0, 0, 0, 0},  {3, 59, 0, 0, 0, 0},  {4, 60, 0, 0, 0, 0},
    {9, 47, 0, 0, 0, 0},  {10, 48, 0, 0, 0, 0}, {11, 61, 0, 0, 0, 0},
    {12, 62, 0, 0, 0, 0}, {13, 49, 0, 0, 0, 0}, {14, 50, 0, 0, 0, 0},
    {15, 66, 0, 0, 0, 0}, {16, 67, 0, 0, 0, 0},
    {17, 32, 68, 0, 0, 0}, {18, 33, 69, 0, 0, 0}, {19, 34, 70, 0, 0, 0},
    {20, 35, 71, 0, 0, 0}, {21, 36, 72, 0, 0, 0}, {22, 37, 73, 0, 0, 0},
    {23, 0, 0, 0, 0, 0},  {24, 0, 0, 0, 0, 0},
    {25, 38, 0, 0, 0, 0}, {26, 39, 0, 0, 0, 0},
    {27, 40, 74, 0, 0, 0}, {28, 41, 75, 0, 0, 0}
};

// ---------------------------------------------------------------------------
// Dynamic SMEM layout
//   A tiles: 128 rows x 64 fp16, row stride 144 B (128 B data + 16 B pad so
//   ldmatrix row addresses are conflict-free).  hi and lo copies.
//   Bfrag: per-lane mma B fragments for W2, hi and lo (2048 words each).
// ---------------------------------------------------------------------------
#define A_STRIDE   144
#define SM_AHI     0                       // 128*144 = 18432 B
#define SM_ALO     18432                   // 18432 B
#define SM_BFRAG   36864                   // 16384 B (hi 8192 | lo 8192)
#define SM_W1      53248                   // 128 floats
#define SM_B1      53760                   // 64 floats
#define SM_B2      54016                   // 64 floats
#define SM_WOUT    54272                   // 64 floats
#define SMEM_TOTAL 54528

// ---------------------------------------------------------------------------
// Warp-level tensor-core primitives (sm_80 baseline PTX -> compiles at
// compute_103; no sm_103a-only features).
// ---------------------------------------------------------------------------
__device__ __forceinline__ void ldmatrix_x4(uint32_t& r0, uint32_t& r1,
                                            uint32_t& r2, uint32_t& r3,
                                            uint32_t addr) {
    asm volatile("ldmatrix.sync.aligned.m8n8.x4.shared.b16 {%0,%1,%2,%3}, [%4];"
                 : "=r"(r0), "=r"(r1), "=r"(r2), "=r"(r3) : "r"(addr));
}
__device__ __forceinline__ void mma16816(float* c, const uint32_t* a,
                                         uint32_t b0, uint32_t b1) {
    asm volatile(
        "mma.sync.aligned.m16n8k16.row.col.f32.f16.f16.f32 "
        "{%0,%1,%2,%3}, {%4,%5,%6,%7}, {%8,%9}, {%0,%1,%2,%3};"
        : "+f"(c[0]), "+f"(c[1]), "+f"(c[2]), "+f"(c[3])
        : "r"(a[0]), "r"(a[1]), "r"(a[2]), "r"(a[3]), "r"(b0), "r"(b1));
}
__device__ __forceinline__ uint32_t smem_to_u32(const void* p) {
    uint32_t a;
    asm("{ .reg .u64 t; cvta.to.shared.u64 t, %1; cvt.u32.u64 %0, t; }" : "=r"(a) : "l"(p));
    return a;
}
__device__ __forceinline__ uint32_t pack_h2(float lo_val, float hi_val) {
    __half2 h = __halves2half2(__float2half_rn(lo_val), __float2half_rn(hi_val));
    return *reinterpret_cast<uint32_t*>(&h);
}

// ---------------------------------------------------------------------------
// Pass 1: HMMA MLP.  grid = (CHUNKS, 74), block = 128 (4 warps).
// Each warp: 32 points = 2 m16 tiles; N=64 = 8 n8 tiles; K=64 = 4 k16 tiles.
// fp16 hi/lo split of A (=h1) and B (=W2): 3 MMAs per (m,n,k) tile.
// ---------------------------------------------------------------------------
__global__ void __launch_bounds__(128)
mlp_hmma_kernel(const float* __restrict__ t_p,
                const float* __restrict__ comp,
                const float* __restrict__ W1,
                const float* __restrict__ b1,
                const float* __restrict__ W2,
                const float* __restrict__ b2,
                const float* __restrict__ Wout,
                const float* __restrict__ bout)
{
    extern __shared__ char smem[];
    const uint32_t sb = smem_to_u32(smem);
    const int tid  = threadIdx.x;
    const int lane = tid & 31;
    const int warp = tid >> 5;
    const int g = c_net_id[blockIdx.y];

    float* sW1v   = (float*)(smem + SM_W1);
    float* sb1v   = (float*)(smem + SM_B1);
    float* sb2v   = (float*)(smem + SM_B2);
    float* swoutv = (float*)(smem + SM_WOUT);
    uint32_t* sBhi = (uint32_t*)(smem + SM_BFRAG);
    uint32_t* sBlo = sBhi + 2048;

    // ---- stage W2[g] coalesced into the (not yet used) A area ----
    float* sW2stage = (float*)(smem + SM_AHI);
    {
        const float4* src = (const float4*)(W2 + g * 4096);
        float4* dst = (float4*)sW2stage;
        #pragma unroll
        for (int i = 0; i < 8; i++) dst[tid + 128 * i] = src[tid + 128 * i];
        sW1v[tid] = W1[g * 128 + tid];
        if (tid < 64) {
            sb1v[tid]   = b1[g * 64 + tid];
            sb2v[tid]   = b2[g * 64 + tid];
            swoutv[tid] = Wout[g * 64 + tid];
        }
    }
    __syncthreads();

    // ---- build per-lane B fragments (mma.m16n8k16 col-layout):
    //   word index = ((kt*8+nt)*32 + lane)*2 + reg
    //   reg r, lane l: k = kt*16 + (l&3)*2 + (r?8:0) (+1 for 2nd half), n = nt*8 + (l>>2)
    //   B[k][n] = W2[g][h=k][out=n]
    #pragma unroll
    for (int ii = 0; ii < 16; ii++) {
        int idx  = tid + ii * 128;          // 0..2047
        int reg  = idx & 1;
        int l    = (idx >> 1) & 31;
        int ktnt = idx >> 6;                // kt*8+nt
        int kt = ktnt >> 3, nt = ktnt & 7;
        int k = kt * 16 + (l & 3) * 2 + (reg ? 8 : 0);
        int n = nt * 8 + (l >> 2);
        float w0 = sW2stage[k * 64 + n];
        float w1 = sW2stage[(k + 1) * 64 + n];
        float w0h = __half2float(__float2half_rn(w0));
        float w1h = __half2float(__float2half_rn(w1));
        sBhi[idx] = pack_h2(w0h, w1h);
        sBlo[idx] = pack_h2(w0 - w0h, w1 - w1h);
    }
    __syncthreads();

    const float bias_out = bout[g];
    const int cg = (g < 29) ? 0 : (g < 42) ? 1 : (g < 51) ? 2
                 : (g < 54) ? 3 : (g < 63) ? 4 : 5;
    const float2* __restrict__ tp2 = (const float2*)t_p;

    for (int t = 0; t < TILES_PER_CTA; t++) {
        const int tilebase = (blockIdx.x * TILES_PER_CTA + t) * 128;

        // ---- layer 1 (exact fp32), split hi/lo -> A tiles ----
        {
            const float2 tp = tp2[tilebase + tid];
            char* rowhi = smem + SM_AHI + tid * A_STRIDE;
            char* rowlo = smem + SM_ALO + tid * A_STRIDE;
            #pragma unroll
            for (int j = 0; j < 64; j += 2) {
                float h0 = fmaxf(fmaf(tp.x, sW1v[j],     fmaf(tp.y, sW1v[64 + j],     sb1v[j])),     0.0f);
                float h1 = fmaxf(fmaf(tp.x, sW1v[j + 1], fmaf(tp.y, sW1v[64 + j + 1], sb1v[j + 1])), 0.0f);
                float h0h = __half2float(__float2half_rn(h0));
                float h1h = __half2float(__float2half_rn(h1));
                *(uint32_t*)(rowhi + j * 2) = pack_h2(h0h, h1h);
                *(uint32_t*)(rowlo + j * 2) = pack_h2(h0 - h0h, h1 - h1h);
            }
        }
        __syncthreads();

        // ---- warp GEMM: D[32x64] = A[32x64] * B[64x64] (hi/lo split) ----
        float acc[2][8][4];
        #pragma unroll
        for (int mt = 0; mt < 2; mt++)
            #pragma unroll
            for (int nt = 0; nt < 8; nt++)
                #pragma unroll
                for (int q = 0; q < 4; q++) acc[mt][nt][q] = 0.0f;

        #pragma unroll
        for (int kt = 0; kt < 4; kt++) {
            uint32_t ahi[2][4], alo[2][4];
            #pragma unroll
            for (int mt = 0; mt < 2; mt++) {
                int row = warp * 32 + mt * 16 + (lane & 15);
                uint32_t off = (uint32_t)(row * A_STRIDE + kt * 32 + ((lane >> 4) * 16));
                ldmatrix_x4(ahi[mt][0], ahi[mt][1], ahi[mt][2], ahi[mt][3], sb + SM_AHI + off);
                ldmatrix_x4(alo[mt][0], alo[mt][1], alo[mt][2], alo[mt][3], sb + SM_ALO + off);
            }
            #pragma unroll
            for (int nt = 0; nt < 8; nt++) {
                uint32_t fidx = (uint32_t)(((kt * 8 + nt) * 32 + lane) * 2);
                uint2 bhi = *(uint2*)(sBhi + fidx);
                uint2 blo = *(uint2*)(sBlo + fidx);
                #pragma unroll
                for (int mt = 0; mt < 2; mt++) {
                    mma16816(acc[mt][nt], ahi[mt], bhi.x, bhi.y);   // hi*hi
                    mma16816(acc[mt][nt], ahi[mt], blo.x, blo.y);   // hi*lo
                    mma16816(acc[mt][nt], alo[mt], bhi.x, bhi.y);   // lo*hi
                }
            }
        }

        // ---- layer 3 epilogue: ke = relu(sum_n relu(acc+b2)*wout + bout) ----
        #pragma unroll
        for (int mt = 0; mt < 2; mt++) {
            float kp0 = 0.0f, kp1 = 0.0f;   // rows (lane>>2) and (lane>>2)+8
            #pragma unroll
            for (int nt = 0; nt < 8; nt++) {
                int n0 = nt * 8 + (lane & 3) * 2;
                float b20 = sb2v[n0],     w0 = swoutv[n0];
                float b21 = sb2v[n0 + 1], w1 = swoutv[n0 + 1];
                kp0 = fmaf(fmaxf(acc[mt][nt][0] + b20, 0.0f), w0, kp0);
                kp0 = fmaf(fmaxf(acc[mt][nt][1] + b21, 0.0f), w1, kp0);
                kp1 = fmaf(fmaxf(acc[mt][nt][2] + b20, 0.0f), w0, kp1);
                kp1 = fmaf(fmaxf(acc[mt][nt][3] + b21, 0.0f), w1, kp1);
            }
            kp0 += __shfl_xor_sync(0xFFFFFFFF, kp0, 1);
            kp0 += __shfl_xor_sync(0xFFFFFFFF, kp0, 2);
            kp1 += __shfl_xor_sync(0xFFFFFFFF, kp1, 1);
            kp1 += __shfl_xor_sync(0xFFFFFFFF, kp1, 2);
            if ((lane & 3) == 0) {
                int r0 = tilebase + warp * 32 + mt * 16 + (lane >> 2);
                float ke0 = fmaxf(kp0 + bias_out, 0.0f);
                float ke1 = fmaxf(kp1 + bias_out, 0.0f);
                g_tau[g * NPTS + r0]     = ke0 * comp[cg * NPTS + r0];
                g_tau[g * NPTS + r0 + 8] = ke1 * comp[cg * NPTS + r0 + 8];
            }
        }
        __syncthreads();   // A tiles reused next iteration
    }
}

// ---------------------------------------------------------------------------
// Pass 2: gather per-channel net contributions + the two broadcast products.
// Output layout: [tau_gases(29,N) | tau_lw(29,N) | tau_iw(29,N)]  fp32.
// ---------------------------------------------------------------------------
__global__ void combine_kernel(const float* __restrict__ comp,
                               const float* __restrict__ ke_lw,
                               const float* __restrict__ ke_iw,
                               float* __restrict__ out)
{
    const int c = blockIdx.y;
    const int n = blockIdx.x * blockDim.x + threadIdx.x;

    const int cnt = c_ch_cnt[c];
    float s = 0.0f;
    #pragma unroll
    for (int i = 0; i < 6; i++)
        if (i < cnt) s += g_tau[c_ch_nets[c][i] * NPTS + n];

    out[c * NPTS + n] = s;
    out[29 * NPTS + c * NPTS + n] = ke_lw[c] * comp[6 * NPTS + n];
    out[58 * NPTS + c * NPTS + n] = ke_iw[c] * comp[7 * NPTS + n];
}

// ---------------------------------------------------------------------------
// Launch contract
// ---------------------------------------------------------------------------
extern "C" void kernel_launch(void* const* d_in, const int* in_sizes, int n_in,
                              void* d_out, int out_size)
{
    const float* t_p   = (const float*)d_in[0];
    const float* comp  = (const float*)d_in[1];
    const float* W1    = (const float*)d_in[2];
    const float* b1    = (const float*)d_in[3];
    const float* W2    = (const float*)d_in[4];
    const float* b2    = (const float*)d_in[5];
    const float* Wout  = (const float*)d_in[6];
    const float* bout  = (const float*)d_in[7];
    const float* ke_lw = (const float*)d_in[8];
    const float* ke_iw = (const float*)d_in[9];
    float* out = (float*)d_out;

    cudaFuncSetAttribute(mlp_hmma_kernel,
                         cudaFuncAttributeMaxDynamicSharedMemorySize, SMEM_TOTAL);

    dim3 grid1(CHUNKS, 74);
    mlp_hmma_kernel<<<grid1, 128, SMEM_TOTAL>>>(t_p, comp, W1, b1, W2, b2, Wout, bout);

    dim3 grid2(NPTS / 256, 29);
    combine_kernel<<<grid2, 256>>>(comp, ke_lw, ke_iw, out);
}

// round 16
// speedup vs baseline: 3.2984x; 1.0002x over previous
#include <cuda_runtime.h>
#include <cuda_fp16.h>
#include <cstdint>

#define NPTS 32768
#define TILES_PER_CTA 16
#define CHUNKS 16          // CHUNKS * TILES_PER_CTA * 128 == NPTS

// ---------------------------------------------------------------------------
// Scratch: per-net optical depth tau[g][n]
// ---------------------------------------------------------------------------
__device__ float g_tau[76 * NPTS];

// Active nets (h2o nets 7,8 are dead: never referenced by H2O_IDX).
__constant__ int c_net_id[74] = {
    0, 1, 2, 3, 4, 5, 6,
    9, 10, 11, 12, 13, 14, 15, 16, 17, 18, 19, 20, 21, 22, 23, 24, 25, 26, 27, 28,
    29, 30, 31, 32, 33, 34, 35, 36, 37, 38, 39, 40, 41,
    42, 43, 44, 45, 46, 47, 48, 49, 50,
    51, 52, 53,
    54, 55, 56, 57, 58, 59, 60, 61, 62,
    63, 64, 65, 66, 67, 68, 69, 70, 71, 72, 73, 74, 75
};

// Per-channel contributing nets (gather form of the reference scatter-adds).
__constant__ int c_ch_cnt[29] = {
    6, 6, 6, 2, 2, 2, 2, 2, 2, 2, 2, 2, 2, 2, 2, 2, 2,
    3, 3, 3, 3, 3, 3, 1, 1, 2, 2, 3, 3
};
__constant__ int c_ch_nets[29][6] = {
    {0, 29, 42, 51, 54, 63}, {1, 30, 43, 52, 55, 64}, {2, 31, 44, 53, 56, 65},
    {3, 57, 0, 0, 0, 0},  {4, 58, 0, 0, 0, 0},  {5, 45, 0, 0, 0, 0},
    {6, 46, 0, 0, 0, 0},  {3, 59, 0, 0, 0, 0},  {4, 60, 0, 0, 0, 0},
    {9, 47, 0, 0, 0, 0},  {10, 48, 0, 0, 0, 0}, {11, 61, 0, 0, 0, 0},
    {12, 62, 0, 0, 0, 0}, {13, 49, 0, 0, 0, 0}, {14, 50, 0, 0, 0, 0},
    {15, 66, 0, 0, 0, 0}, {16, 67, 0, 0, 0, 0},
    {17, 32, 68, 0, 0, 0}, {18, 33, 69, 0, 0, 0}, {19, 34, 70, 0, 0, 0},
    {20, 35, 71, 0, 0, 0}, {21, 36, 72, 0, 0, 0}, {22, 37, 73, 0, 0, 0},
    {23, 0, 0, 0, 0, 0},  {24, 0, 0, 0, 0, 0},
    {25, 38, 0, 0, 0, 0}, {26, 39, 0, 0, 0, 0},
    {27, 40, 74, 0, 0, 0}, {28, 41, 75, 0, 0, 0}
};

// ---------------------------------------------------------------------------
// Dynamic SMEM layout
//   A tiles: 128 rows x 64 fp16, row stride 144 B (128 B data + 16 B pad so
//   ldmatrix row addresses are conflict-free).  hi and lo copies.
//   Bfrag: per-lane mma B fragments for W2, hi and lo (2048 words each).
// ---------------------------------------------------------------------------
#define A_STRIDE   144
#define SM_AHI     0                       // 128*144 = 18432 B
#define SM_ALO     18432                   // 18432 B
#define SM_BFRAG   36864                   // 16384 B (hi 8192 | lo 8192)
#define SM_W1      53248                   // 128 floats
#define SM_B1      53760                   // 64 floats
#define SM_B2      54016                   // 64 floats
#define SM_WOUT    54272                   // 64 floats
#define SMEM_TOTAL 54528

// ---------------------------------------------------------------------------
// Warp-level tensor-core primitives (sm_80 baseline PTX -> compiles at
// compute_103; no sm_103a-only features).
// ---------------------------------------------------------------------------
__device__ __forceinline__ void ldmatrix_x4(uint32_t& r0, uint32_t& r1,
                                            uint32_t& r2, uint32_t& r3,
                                            uint32_t addr) {
    asm volatile("ldmatrix.sync.aligned.m8n8.x4.shared.b16 {%0,%1,%2,%3}, [%4];"
                 : "=r"(r0), "=r"(r1), "=r"(r2), "=r"(r3) : "r"(addr));
}
__device__ __forceinline__ void mma16816(float* c, const uint32_t* a,
                                         uint32_t b0, uint32_t b1) {
    asm volatile(
        "mma.sync.aligned.m16n8k16.row.col.f32.f16.f16.f32 "
        "{%0,%1,%2,%3}, {%4,%5,%6,%7}, {%8,%9}, {%0,%1,%2,%3};"
        : "+f"(c[0]), "+f"(c[1]), "+f"(c[2]), "+f"(c[3])
        : "r"(a[0]), "r"(a[1]), "r"(a[2]), "r"(a[3]), "r"(b0), "r"(b1));
}
__device__ __forceinline__ uint32_t smem_to_u32(const void* p) {
    uint32_t a;
    asm("{ .reg .u64 t; cvta.to.shared.u64 t, %1; cvt.u32.u64 %0, t; }" : "=r"(a) : "l"(p));
    return a;
}
__device__ __forceinline__ uint32_t pack_h2(float lo_val, float hi_val) {
    __half2 h = __halves2half2(__float2half_rn(lo_val), __float2half_rn(hi_val));
    return *reinterpret_cast<uint32_t*>(&h);
}

// ---------------------------------------------------------------------------
// Pass 1: HMMA MLP.  grid = (CHUNKS, 74), block = 128 (4 warps).
// Each warp: 32 points = 2 m16 tiles; N=64 = 8 n8 tiles; K=64 = 4 k16 tiles.
// fp16 hi/lo split of A (=h1) and B (=W2): 3 MMAs per (m,n,k) tile.
// ---------------------------------------------------------------------------
__global__ void __launch_bounds__(128)
mlp_hmma_kernel(const float* __restrict__ t_p,
                const float* __restrict__ comp,
                const float* __restrict__ W1,
                const float* __restrict__ b1,
                const float* __restrict__ W2,
                const float* __restrict__ b2,
                const float* __restrict__ Wout,
                const float* __restrict__ bout)
{
    extern __shared__ char smem[];
    const uint32_t sb = smem_to_u32(smem);
    const int tid  = threadIdx.x;
    const int lane = tid & 31;
    const int warp = tid >> 5;
    const int g = c_net_id[blockIdx.y];

    float* sW1v   = (float*)(smem + SM_W1);
    float* sb1v   = (float*)(smem + SM_B1);
    float* sb2v   = (float*)(smem + SM_B2);
    float* swoutv = (float*)(smem + SM_WOUT);
    uint32_t* sBhi = (uint32_t*)(smem + SM_BFRAG);
    uint32_t* sBlo = sBhi + 2048;

    // ---- stage W2[g] coalesced into the (not yet used) A area ----
    float* sW2stage = (float*)(smem + SM_AHI);
    {
        const float4* src = (const float4*)(W2 + g * 4096);
        float4* dst = (float4*)sW2stage;
        #pragma unroll
        for (int i = 0; i < 8; i++) dst[tid + 128 * i] = src[tid + 128 * i];
        sW1v[tid] = W1[g * 128 + tid];
        if (tid < 64) {
            sb1v[tid]   = b1[g * 64 + tid];
            sb2v[tid]   = b2[g * 64 + tid];
            swoutv[tid] = Wout[g * 64 + tid];
        }
    }
    __syncthreads();

    // ---- build per-lane B fragments (mma.m16n8k16 col-layout):
    //   word index = ((kt*8+nt)*32 + lane)*2 + reg
    //   reg r, lane l: k = kt*16 + (l&3)*2 + (r?8:0) (+1 for 2nd half), n = nt*8 + (l>>2)
    //   B[k][n] = W2[g][h=k][out=n]
    #pragma unroll
    for (int ii = 0; ii < 16; ii++) {
        int idx  = tid + ii * 128;          // 0..2047
        int reg  = idx & 1;
        int l    = (idx >> 1) & 31;
        int ktnt = idx >> 6;                // kt*8+nt
        int kt = ktnt >> 3, nt = ktnt & 7;
        int k = kt * 16 + (l & 3) * 2 + (reg ? 8 : 0);
        int n = nt * 8 + (l >> 2);
        float w0 = sW2stage[k * 64 + n];
        float w1 = sW2stage[(k + 1) * 64 + n];
        float w0h = __half2float(__float2half_rn(w0));
        float w1h = __half2float(__float2half_rn(w1));
        sBhi[idx] = pack_h2(w0h, w1h);
        sBlo[idx] = pack_h2(w0 - w0h, w1 - w1h);
    }
    __syncthreads();

    const float bias_out = bout[g];
    const int cg = (g < 29) ? 0 : (g < 42) ? 1 : (g < 51) ? 2
                 : (g < 54) ? 3 : (g < 63) ? 4 : 5;
    const float2* __restrict__ tp2 = (const float2*)t_p;

    for (int t = 0; t < TILES_PER_CTA; t++) {
        const int tilebase = (blockIdx.x * TILES_PER_CTA + t) * 128;

        // ---- layer 1 (exact fp32), split hi/lo -> A tiles ----
        {
            const float2 tp = tp2[tilebase + tid];
            char* rowhi = smem + SM_AHI + tid * A_STRIDE;
            char* rowlo = smem + SM_ALO + tid * A_STRIDE;
            #pragma unroll
            for (int j = 0; j < 64; j += 2) {
                float h0 = fmaxf(fmaf(tp.x, sW1v[j],     fmaf(tp.y, sW1v[64 + j],     sb1v[j])),     0.0f);
                float h1 = fmaxf(fmaf(tp.x, sW1v[j + 1], fmaf(tp.y, sW1v[64 + j + 1], sb1v[j + 1])), 0.0f);
                float h0h = __half2float(__float2half_rn(h0));
                float h1h = __half2float(__float2half_rn(h1));
                *(uint32_t*)(rowhi + j * 2) = pack_h2(h0h, h1h);
                *(uint32_t*)(rowlo + j * 2) = pack_h2(h0 - h0h, h1 - h1h);
            }
        }
        __syncthreads();

        // ---- warp GEMM: D[32x64] = A[32x64] * B[64x64] (hi/lo split) ----
        float acc[2][8][4];
        #pragma unroll
        for (int mt = 0; mt < 2; mt++)
            #pragma unroll
            for (int nt = 0; nt < 8; nt++)
                #pragma unroll
                for (int q = 0; q < 4; q++) acc[mt][nt][q] = 0.0f;

        #pragma unroll
        for (int kt = 0; kt < 4; kt++) {
            uint32_t ahi[2][4], alo[2][4];
            #pragma unroll
            for (int mt = 0; mt < 2; mt++) {
                int row = warp * 32 + mt * 16 + (lane & 15);
                uint32_t off = (uint32_t)(row * A_STRIDE + kt * 32 + ((lane >> 4) * 16));
                ldmatrix_x4(ahi[mt][0], ahi[mt][1], ahi[mt][2], ahi[mt][3], sb + SM_AHI + off);
                ldmatrix_x4(alo[mt][0], alo[mt][1], alo[mt][2], alo[mt][3], sb + SM_ALO + off);
            }
            #pragma unroll
            for (int nt = 0; nt < 8; nt++) {
                uint32_t fidx = (uint32_t)(((kt * 8 + nt) * 32 + lane) * 2);
                uint2 bhi = *(uint2*)(sBhi + fidx);
                uint2 blo = *(uint2*)(sBlo + fidx);
                #pragma unroll
                for (int mt = 0; mt < 2; mt++) {
                    mma16816(acc[mt][nt], ahi[mt], bhi.x, bhi.y);   // hi*hi
                    mma16816(acc[mt][nt], ahi[mt], blo.x, blo.y);   // hi*lo
                    mma16816(acc[mt][nt], alo[mt], bhi.x, bhi.y);   // lo*hi
                }
            }
        }

        // ---- layer 3 epilogue: ke = relu(sum_n relu(acc+b2)*wout + bout) ----
        #pragma unroll
        for (int mt = 0; mt < 2; mt++) {
            float kp0 = 0.0f, kp1 = 0.0f;   // rows (lane>>2) and (lane>>2)+8
            #pragma unroll
            for (int nt = 0; nt < 8; nt++) {
                int n0 = nt * 8 + (lane & 3) * 2;
                float b20 = sb2v[n0],     w0 = swoutv[n0];
                float b21 = sb2v[n0 + 1], w1 = swoutv[n0 + 1];
                kp0 = fmaf(fmaxf(acc[mt][nt][0] + b20, 0.0f), w0, kp0);
                kp0 = fmaf(fmaxf(acc[mt][nt][1] + b21, 0.0f), w1, kp0);
                kp1 = fmaf(fmaxf(acc[mt][nt][2] + b20, 0.0f), w0, kp1);
                kp1 = fmaf(fmaxf(acc[mt][nt][3] + b21, 0.0f), w1, kp1);
            }
            kp0 += __shfl_xor_sync(0xFFFFFFFF, kp0, 1);
            kp0 += __shfl_xor_sync(0xFFFFFFFF, kp0, 2);
            kp1 += __shfl_xor_sync(0xFFFFFFFF, kp1, 1);
            kp1 += __shfl_xor_sync(0xFFFFFFFF, kp1, 2);
            if ((lane & 3) == 0) {
                int r0 = tilebase + warp * 32 + mt * 16 + (lane >> 2);
                float ke0 = fmaxf(kp0 + bias_out, 0.0f);
                float ke1 = fmaxf(kp1 + bias_out, 0.0f);
                g_tau[g * NPTS + r0]     = ke0 * comp[cg * NPTS + r0];
                g_tau[g * NPTS + r0 + 8] = ke1 * comp[cg * NPTS + r0 + 8];
            }
        }
        __syncthreads();   // A tiles reused next iteration
    }
}

// ---------------------------------------------------------------------------
// Pass 2: gather per-channel net contributions + the two broadcast products.
// Output layout: [tau_gases(29,N) | tau_lw(29,N) | tau_iw(29,N)]  fp32.
// ---------------------------------------------------------------------------
__global__ void combine_kernel(const float* __restrict__ comp,
                               const float* __restrict__ ke_lw,
                               const float* __restrict__ ke_iw,
                               float* __restrict__ out)
{
    const int c = blockIdx.y;
    const int n = blockIdx.x * blockDim.x + threadIdx.x;

    const int cnt = c_ch_cnt[c];
    float s = 0.0f;
    #pragma unroll
    for (int i = 0; i < 6; i++)
        if (i < cnt) s += g_tau[c_ch_nets[c][i] * NPTS + n];

    out[c * NPTS + n] = s;
    out[29 * NPTS + c * NPTS + n] = ke_lw[c] * comp[6 * NPTS + n];
    out[58 * NPTS + c * NPTS + n] = ke_iw[c] * comp[7 * NPTS + n];
}

// ---------------------------------------------------------------------------
// Launch contract
// ---------------------------------------------------------------------------
extern "C" void kernel_launch(void* const* d_in, const int* in_sizes, int n_in,
                              void* d_out, int out_size)
{
    const float* t_p   = (const float*)d_in[0];
    const float* comp  = (const float*)d_in[1];
    const float* W1    = (const float*)d_in[2];
    const float* b1    = (const float*)d_in[3];
    const float* W2    = (const float*)d_in[4];
    const float* b2    = (const float*)d_in[5];
    const float* Wout  = (const float*)d_in[6];
    const float* bout  = (const float*)d_in[7];
    const float* ke_lw = (const float*)d_in[8];
    const float* ke_iw = (const float*)d_in[9];
    float* out = (float*)d_out;

    cudaFuncSetAttribute(mlp_hmma_kernel,
                         cudaFuncAttributeMaxDynamicSharedMemorySize, SMEM_TOTAL);

    dim3 grid1(CHUNKS, 74);
    mlp_hmma_kernel<<<grid1, 128, SMEM_TOTAL>>>(t_p, comp, W1, b1, W2, b2, Wout, bout);

    dim3 grid2(NPTS / 256, 29);
    combine_kernel<<<grid2, 256>>>(comp, ke_lw, ke_iw, out);
}